// round 1
// baseline (speedup 1.0000x reference)
#include <cuda_runtime.h>
#include <math.h>

#define SEQ    2048
#define NROWS  4096          // b * n
#define NHEADS 16

// ---------------- scratch (no allocations allowed) ----------------
__device__ float g_q1 [NROWS * 512];     //  8.4 MB
__device__ float g_q  [NROWS * 3072];    // 50.3 MB  (b*n, h*192) after rope
__device__ float g_ckv[NROWS * 576];     //  9.4 MB  (compressed 512 | k_pe 64)
__device__ float g_kv [NROWS * 4096];    // 67.1 MB  (h*256: k_nope 128 | v 128)
__device__ float g_att[NROWS * 2048];    // 33.5 MB  (b*n, h*128)

// ---------------- generic tiled SGEMM: C[M,N] = A[M,K] @ B[K,N] ----------------
// BM=128, BN=128, BK=8, 256 threads, 8x8 per-thread tile.
// Assumes M % 128 == 0, K % 8 == 0; N guarded.
__global__ __launch_bounds__(256) void sgemm_kernel(
    const float* __restrict__ A, int lda,
    const float* __restrict__ B, int ldb,
    float* __restrict__ C, int ldc,
    int M, int N, int K)
{
    __shared__ float As[8][128];
    __shared__ float Bs[8][128];
    const int tid = threadIdx.x;
    const int rowBase = blockIdx.y * 128;
    const int colBase = blockIdx.x * 128;

    const int arow = tid >> 1;
    const int acol = (tid & 1) * 4;
    const int brow = tid >> 5;
    const int bcol = (tid & 31) * 4;

    const int tx = tid & 15;
    const int ty = tid >> 4;

    float acc[8][8];
    #pragma unroll
    for (int i = 0; i < 8; i++)
        #pragma unroll
        for (int j = 0; j < 8; j++) acc[i][j] = 0.f;

    for (int k0 = 0; k0 < K; k0 += 8) {
        float4 av = *reinterpret_cast<const float4*>(
            A + (size_t)(rowBase + arow) * lda + k0 + acol);
        As[acol + 0][arow] = av.x;
        As[acol + 1][arow] = av.y;
        As[acol + 2][arow] = av.z;
        As[acol + 3][arow] = av.w;

        int bc = colBase + bcol;
        const float* Bp = B + (size_t)(k0 + brow) * ldb + bc;
        float4 bv;
        if (bc + 3 < N) {
            bv = *reinterpret_cast<const float4*>(Bp);
        } else {
            bv.x = (bc + 0 < N) ? Bp[0] : 0.f;
            bv.y = (bc + 1 < N) ? Bp[1] : 0.f;
            bv.z = (bc + 2 < N) ? Bp[2] : 0.f;
            bv.w = (bc + 3 < N) ? Bp[3] : 0.f;
        }
        *reinterpret_cast<float4*>(&Bs[brow][bcol]) = bv;
        __syncthreads();

        #pragma unroll
        for (int k = 0; k < 8; k++) {
            float4 a0 = *reinterpret_cast<const float4*>(&As[k][ty * 8]);
            float4 a1 = *reinterpret_cast<const float4*>(&As[k][ty * 8 + 4]);
            float4 b0 = *reinterpret_cast<const float4*>(&Bs[k][tx * 8]);
            float4 b1 = *reinterpret_cast<const float4*>(&Bs[k][tx * 8 + 4]);
            float ra[8] = {a0.x, a0.y, a0.z, a0.w, a1.x, a1.y, a1.z, a1.w};
            float rb[8] = {b0.x, b0.y, b0.z, b0.w, b1.x, b1.y, b1.z, b1.w};
            #pragma unroll
            for (int i = 0; i < 8; i++)
                #pragma unroll
                for (int j = 0; j < 8; j++) acc[i][j] += ra[i] * rb[j];
        }
        __syncthreads();
    }

    if (colBase + 128 <= N) {
        #pragma unroll
        for (int i = 0; i < 8; i++) {
            size_t r = (size_t)(rowBase + ty * 8 + i) * ldc + colBase + tx * 8;
            *reinterpret_cast<float4*>(C + r)     = make_float4(acc[i][0], acc[i][1], acc[i][2], acc[i][3]);
            *reinterpret_cast<float4*>(C + r + 4) = make_float4(acc[i][4], acc[i][5], acc[i][6], acc[i][7]);
        }
    } else {
        #pragma unroll
        for (int i = 0; i < 8; i++) {
            int r = rowBase + ty * 8 + i;
            #pragma unroll
            for (int j = 0; j < 8; j++) {
                int cc = colBase + tx * 8 + j;
                if (cc < N) C[(size_t)r * ldc + cc] = acc[i][j];
            }
        }
    }
}

// ---------------- RoPE: interleaved pairs, applied in place ----------------
// grid = 4096 rows (b*n); 17 warps: warps 0-15 -> q_pe per head, warp 16 -> k_pe.
__global__ void rope_kernel()
{
    const int row  = blockIdx.x;
    const int pos  = row & (SEQ - 1);
    const int warp = threadIdx.x >> 5;
    const int lane = threadIdx.x & 31;

    // theta_j = 10000^{-j/32}; compute angle in double for accuracy
    double theta = exp(-9.210340371976184 * (double)lane / 32.0);
    double ang = (double)pos * theta;
    float c = (float)cos(ang);
    float s = (float)sin(ang);

    float* p;
    if (warp < 16)
        p = g_q + (size_t)row * 3072 + warp * 192 + 128 + 2 * lane;
    else
        p = g_ckv + (size_t)row * 576 + 512 + 2 * lane;

    float x1 = p[0], x2 = p[1];
    p[0] = x1 * c - x2 * s;
    p[1] = x1 * s + x2 * c;
}

// ---------------- flash attention ----------------
// Block: 256 threads. 64 queries x (stream 32-key tiles). d_qk = 192, d_v = 128.
// Thread (g = tid/8, c = tid%8): rows {2g, 2g+1}; score cols c*4..c*4+3; out cols c*16..c*16+15.
#define QS_LD 196
#define KS_LD 196
#define VS_LD 132
#define PS_LD 33
#define SMEM_ATTN ((64 * QS_LD + 32 * KS_LD + 32 * VS_LD + 64 * PS_LD) * 4)

__global__ __launch_bounds__(256, 1) void attn_kernel()
{
    extern __shared__ float sm[];
    float* Qs = sm;                    // [64][196]
    float* Ks = Qs + 64 * QS_LD;       // [32][196]
    float* Vs = Ks + 32 * KS_LD;       // [32][132]
    float* Ps = Vs + 32 * VS_LD;       // [64][33]

    const int b = blockIdx.z, h = blockIdx.y;
    const int q0 = blockIdx.x * 64;
    const int tid = threadIdx.x;
    const int g = tid >> 3;
    const int c = tid & 7;
    const float scale = 0.07216878364870323f;   // 1/sqrt(192)

    // stage Q tile (rows q0..q0+63, 192 dims)
    for (int i = tid; i < 64 * 48; i += 256) {
        int r = i / 48, d4 = i - r * 48;
        float4 v = reinterpret_cast<const float4*>(
            g_q + (size_t)(b * SEQ + q0 + r) * 3072 + h * 192)[d4];
        reinterpret_cast<float4*>(Qs + r * QS_LD)[d4] = v;
    }

    const int qrow0 = q0 + 2 * g;
    const int qrow1 = qrow0 + 1;

    float m0 = -INFINITY, m1 = -INFINITY, l0 = 0.f, l1 = 0.f;
    float acc0[16], acc1[16];
    #pragma unroll
    for (int i = 0; i < 16; i++) { acc0[i] = 0.f; acc1[i] = 0.f; }

    for (int k0 = 0; k0 < q0 + 64; k0 += 32) {
        // stage K (nope 128 | pe 64) and V tiles
        for (int i = tid; i < 32 * 32; i += 256) {
            int r = i >> 5, d4 = i & 31;
            reinterpret_cast<float4*>(Ks + r * KS_LD)[d4] =
                reinterpret_cast<const float4*>(
                    g_kv + (size_t)(b * SEQ + k0 + r) * 4096 + h * 256)[d4];
        }
        for (int i = tid; i < 32 * 16; i += 256) {
            int r = i >> 4, d4 = i & 15;
            reinterpret_cast<float4*>(Ks + r * KS_LD + 128)[d4] =
                reinterpret_cast<const float4*>(
                    g_ckv + (size_t)(b * SEQ + k0 + r) * 576 + 512)[d4];
        }
        for (int i = tid; i < 32 * 32; i += 256) {
            int r = i >> 5, d4 = i & 31;
            reinterpret_cast<float4*>(Vs + r * VS_LD)[d4] =
                reinterpret_cast<const float4*>(
                    g_kv + (size_t)(b * SEQ + k0 + r) * 4096 + h * 256 + 128)[d4];
        }
        __syncthreads();

        // S = Q Kt : per-thread 2x4
        float sA[4] = {0, 0, 0, 0}, sB[4] = {0, 0, 0, 0};
        const float4* qp0 = reinterpret_cast<const float4*>(Qs + (2 * g)     * QS_LD);
        const float4* qp1 = reinterpret_cast<const float4*>(Qs + (2 * g + 1) * QS_LD);
        const float4* kp0 = reinterpret_cast<const float4*>(Ks + (c * 4 + 0) * KS_LD);
        const float4* kp1 = reinterpret_cast<const float4*>(Ks + (c * 4 + 1) * KS_LD);
        const float4* kp2 = reinterpret_cast<const float4*>(Ks + (c * 4 + 2) * KS_LD);
        const float4* kp3 = reinterpret_cast<const float4*>(Ks + (c * 4 + 3) * KS_LD);
        #pragma unroll 8
        for (int d4 = 0; d4 < 48; d4++) {
            float4 qa = qp0[d4], qb = qp1[d4];
            float4 k;
            k = kp0[d4];
            sA[0] += qa.x*k.x + qa.y*k.y + qa.z*k.z + qa.w*k.w;
            sB[0] += qb.x*k.x + qb.y*k.y + qb.z*k.z + qb.w*k.w;
            k = kp1[d4];
            sA[1] += qa.x*k.x + qa.y*k.y + qa.z*k.z + qa.w*k.w;
            sB[1] += qb.x*k.x + qb.y*k.y + qb.z*k.z + qb.w*k.w;
            k = kp2[d4];
            sA[2] += qa.x*k.x + qa.y*k.y + qa.z*k.z + qa.w*k.w;
            sB[2] += qb.x*k.x + qb.y*k.y + qb.z*k.z + qb.w*k.w;
            k = kp3[d4];
            sA[3] += qa.x*k.x + qa.y*k.y + qa.z*k.z + qa.w*k.w;
            sB[3] += qb.x*k.x + qb.y*k.y + qb.z*k.z + qb.w*k.w;
        }

        // causal mask + scale
        #pragma unroll
        for (int j = 0; j < 4; j++) {
            int kidx = k0 + c * 4 + j;
            sA[j] = (kidx <= qrow0) ? sA[j] * scale : -INFINITY;
            sB[j] = (kidx <= qrow1) ? sB[j] * scale : -INFINITY;
        }

        // online softmax: row spread over 8 consecutive lanes
        float t0 = fmaxf(fmaxf(sA[0], sA[1]), fmaxf(sA[2], sA[3]));
        float t1 = fmaxf(fmaxf(sB[0], sB[1]), fmaxf(sB[2], sB[3]));
        #pragma unroll
        for (int off = 1; off < 8; off <<= 1) {
            t0 = fmaxf(t0, __shfl_xor_sync(0xffffffffu, t0, off));
            t1 = fmaxf(t1, __shfl_xor_sync(0xffffffffu, t1, off));
        }
        float mn0 = fmaxf(m0, t0), mn1 = fmaxf(m1, t1);
        float a0 = expf(m0 - mn0), a1 = expf(m1 - mn1);
        m0 = mn0; m1 = mn1;

        float pA[4], pB[4];
        float ps0 = 0.f, ps1 = 0.f;
        #pragma unroll
        for (int j = 0; j < 4; j++) {
            pA[j] = expf(sA[j] - m0); ps0 += pA[j];
            pB[j] = expf(sB[j] - m1); ps1 += pB[j];
        }
        #pragma unroll
        for (int off = 1; off < 8; off <<= 1) {
            ps0 += __shfl_xor_sync(0xffffffffu, ps0, off);
            ps1 += __shfl_xor_sync(0xffffffffu, ps1, off);
        }
        l0 = l0 * a0 + ps0;
        l1 = l1 * a1 + ps1;

        #pragma unroll
        for (int j = 0; j < 4; j++) {
            Ps[(2 * g)     * PS_LD + c * 4 + j] = pA[j];
            Ps[(2 * g + 1) * PS_LD + c * 4 + j] = pB[j];
        }
        #pragma unroll
        for (int i = 0; i < 16; i++) { acc0[i] *= a0; acc1[i] *= a1; }
        __syncthreads();

        // O += P @ V
        const float* pr0 = Ps + (2 * g)     * PS_LD;
        const float* pr1 = Ps + (2 * g + 1) * PS_LD;
        #pragma unroll 4
        for (int j = 0; j < 32; j++) {
            float p0 = pr0[j], p1 = pr1[j];
            const float4* vr = reinterpret_cast<const float4*>(Vs + j * VS_LD + c * 16);
            #pragma unroll
            for (int i4 = 0; i4 < 4; i4++) {
                float4 v = vr[i4];
                acc0[i4 * 4 + 0] += p0 * v.x; acc0[i4 * 4 + 1] += p0 * v.y;
                acc0[i4 * 4 + 2] += p0 * v.z; acc0[i4 * 4 + 3] += p0 * v.w;
                acc1[i4 * 4 + 0] += p1 * v.x; acc1[i4 * 4 + 1] += p1 * v.y;
                acc1[i4 * 4 + 2] += p1 * v.z; acc1[i4 * 4 + 3] += p1 * v.w;
            }
        }
        __syncthreads();
    }

    float inv0 = 1.f / l0, inv1 = 1.f / l1;
    float* o0 = g_att + (size_t)(b * SEQ + qrow0) * 2048 + h * 128 + c * 16;
    float* o1 = g_att + (size_t)(b * SEQ + qrow1) * 2048 + h * 128 + c * 16;
    #pragma unroll
    for (int i4 = 0; i4 < 4; i4++) {
        reinterpret_cast<float4*>(o0)[i4] = make_float4(
            acc0[i4*4]*inv0, acc0[i4*4+1]*inv0, acc0[i4*4+2]*inv0, acc0[i4*4+3]*inv0);
        reinterpret_cast<float4*>(o1)[i4] = make_float4(
            acc1[i4*4]*inv1, acc1[i4*4+1]*inv1, acc1[i4*4+2]*inv1, acc1[i4*4+3]*inv1);
    }
}

// ---------------- launch ----------------
extern "C" void kernel_launch(void* const* d_in, const int* in_sizes, int n_in,
                              void* d_out, int out_size)
{
    const float* x    = (const float*)d_in[0];
    const float* Wqa  = (const float*)d_in[1];
    const float* Wqb  = (const float*)d_in[2];
    const float* Wkva = (const float*)d_in[3];
    const float* Wkvb = (const float*)d_in[4];
    const float* Wout = (const float*)d_in[5];
    float* out = (float*)d_out;

    float *q1, *q, *ckv, *kv, *att;
    cudaGetSymbolAddress((void**)&q1,  g_q1);
    cudaGetSymbolAddress((void**)&q,   g_q);
    cudaGetSymbolAddress((void**)&ckv, g_ckv);
    cudaGetSymbolAddress((void**)&kv,  g_kv);
    cudaGetSymbolAddress((void**)&att, g_att);

    cudaFuncSetAttribute(attn_kernel,
                         cudaFuncAttributeMaxDynamicSharedMemorySize, SMEM_ATTN);

    dim3 t(256);
    // q1 = x @ Wqa                [4096,2048] x [2048,512]
    sgemm_kernel<<<dim3(4, 32),  t>>>(x, 2048, Wqa, 512,  q1, 512,  4096, 512,  2048);
    // q  = q1 @ Wqb               [4096,512] x [512,3072]
    sgemm_kernel<<<dim3(24, 32), t>>>(q1, 512, Wqb, 3072, q,  3072, 4096, 3072, 512);
    // ckv = x @ Wkva              [4096,2048] x [2048,576]
    sgemm_kernel<<<dim3(5, 32),  t>>>(x, 2048, Wkva, 576, ckv, 576, 4096, 576,  2048);
    // in-place RoPE on q_pe and k_pe
    rope_kernel<<<4096, 544>>>();
    // kv = ckv[:, :512] @ Wkvb    [4096,512] x [512,4096]
    sgemm_kernel<<<dim3(32, 32), t>>>(ckv, 576, Wkvb, 4096, kv, 4096, 4096, 4096, 512);
    // attention -> g_att [4096, 16*128]
    attn_kernel<<<dim3(32, NHEADS, 2), 256, SMEM_ATTN>>>();
    // out = att @ Wout            [4096,2048] x [2048,2048]
    sgemm_kernel<<<dim3(16, 32), t>>>(att, 2048, Wout, 2048, out, 2048, 4096, 2048, 2048);
}